// round 10
// baseline (speedup 1.0000x reference)
#include <cuda_runtime.h>

#define N_ROWS 8000
#define D 9
#define N4 2000            // N_ROWS / 4 (float4 columns)
#define OUT_TPB 256
#define ROWS_PER_BLK 16
#define CHUNK 64           // rows per K1 block
#define NB1 125            // K1 blocks: 125 * 64 = 8000 (all co-resident)
#define K1_TPB 64

// Scratch (device globals — zero-initialized, no allocation allowed)
__device__ float d_csum[NB1];       // per-chunk totals
__device__ float d_spref[NB1];      // exclusive prefix of chunk totals
__device__ float d_w1bar[N_ROWS];   // final normalized weights
__device__ float d_g[N_ROWS];
__device__ float d_h[N_ROWS];
__device__ unsigned int d_tick;     // arrival ticket   (self-resetting)
__device__ unsigned int d_done;     // spref published  (self-resetting)
__device__ unsigned int d_fin;      // finish counter   (self-resetting)

// ---------------------------------------------------------------------------
// K1: fully parallel prologue. 125 blocks (all resident on the 148-SM chip).
//  phase 1 (all blocks):  delta[r] = sum_d[((x-c1)/a1)^2 - ((x-c2)/a2)^2],
//                         per-chunk inclusive cumsum kept in registers,
//                         g/h, chunk totals -> d_csum.
//  phase 2 (last block):  125-element scan -> d_spref, release d_done.
//  phase 3 (all blocks):  short spin (inter-block skew only), then each
//                         thread: w1bar[r] = 1/(1+exp(spref[b] + v)).
//  Self-reset of tick/done/fin for identical graph replays.
// ---------------------------------------------------------------------------
__global__ void __launch_bounds__(K1_TPB)
k_pro(const float* __restrict__ x,
      const float* __restrict__ a1, const float* __restrict__ c1,
      const float* __restrict__ a2, const float* __restrict__ c2,
      const float* __restrict__ wf1, const float* __restrict__ bf1,
      const float* __restrict__ wf2, const float* __restrict__ bf2)
{
    __shared__ float s_w0tot;
    __shared__ float swt[2];
    __shared__ int   s_last;

    const int t = threadIdx.x;
    const int b = blockIdx.x;
    const unsigned lane = t & 31;
    const int w = t >> 5;

    // ---- phase 1: rowstats, one row per thread ----
    const int r = b * CHUNK + t;
    const float inv1 = 1.0f / __ldg(a1);
    const float inv2 = 1.0f / __ldg(a2);
    const float k1 = -__ldg(c1) * inv1;
    const float k2 = -__ldg(c2) * inv2;
    float s1 = 0.f, s2 = 0.f;
    float f1 = __ldg(bf1), f2 = __ldg(bf2);
#pragma unroll
    for (int d = 0; d < D; d++) {
        float xv = __ldg(&x[r * D + d]);
        float u1 = fmaf(xv, inv1, k1);
        float u2 = fmaf(xv, inv2, k2);
        s1 = fmaf(u1, u1, s1);
        s2 = fmaf(u2, u2, s2);
        f1 = fmaf(xv, __ldg(&wf1[d]), f1);
        f2 = fmaf(xv, __ldg(&wf2[d]), f2);
    }
    d_g[r] = f1 - f2;
    d_h[r] = f2;

    // within-chunk inclusive cumsum (2 warps); v stays in a register
    float v = s1 - s2;
#pragma unroll
    for (int o = 1; o < 32; o <<= 1) {
        float n = __shfl_up_sync(0xffffffff, v, o);
        if (lane >= o) v += n;
    }
    if (t == 31) s_w0tot = v;
    __syncthreads();
    if (w == 1) v += s_w0tot;
    if (t == CHUNK - 1) d_csum[b] = v;

    __threadfence();                 // publish csum/g/h before arriving
    __syncthreads();
    if (t == 0) {
        unsigned tk = atomicAdd(&d_tick, 1u);
        s_last = (tk == NB1 - 1u);
    }
    __syncthreads();

    // ---- phase 2: last block scans the 125 chunk totals -> d_spref ----
    if (s_last) {
        __threadfence();             // acquire all blocks' csum
        float c0  = (t < NB1)      ? d_csum[t]      : 0.0f;
        float c1v = (t + 64 < NB1) ? d_csum[t + 64] : 0.0f;

        float a = c0;                // scan chunks 0..63
#pragma unroll
        for (int o = 1; o < 32; o <<= 1) {
            float n = __shfl_up_sync(0xffffffff, a, o);
            if (lane >= o) a += n;
        }
        if (lane == 31) swt[w] = a;
        __syncthreads();
        if (w == 1) a += swt[0];
        float total64 = swt[0] + swt[1];
        d_spref[t] = a - c0;         // exclusive prefix for chunk t
        __syncthreads();

        float bsc = c1v;             // scan chunks 64..124
#pragma unroll
        for (int o = 1; o < 32; o <<= 1) {
            float n = __shfl_up_sync(0xffffffff, bsc, o);
            if (lane >= o) bsc += n;
        }
        if (lane == 31) swt[w] = bsc;
        __syncthreads();
        if (w == 1) bsc += swt[0];
        if (t + 64 < NB1)
            d_spref[t + 64] = total64 + bsc - c1v;

        __syncthreads();
        if (t == 0) {
            __threadfence();         // release spref
            atomicExch(&d_done, 1u);
        }
    } else {
        // ---- short spin: all 125 blocks are co-resident, skew ~1 us ----
        if (t == 0) {
            while (atomicAdd(&d_done, 0u) == 0u) __nanosleep(64);
            __threadfence();         // acquire spref
        }
        __syncthreads();
    }

    // ---- phase 3: parallel apply — ONE exp per thread ----
    const float run = d_spref[b] + v;              // S1[r] - S2[r]
    d_w1bar[r] = 1.0f / (1.0f + __expf(run));

    // ---- self-reset for graph replays ----
    __syncthreads();
    if (t == 0) {
        unsigned fv = atomicAdd(&d_fin, 1u);
        if (fv == NB1 - 1u) {
            atomicExch(&d_tick, 0u);
            atomicExch(&d_done, 0u);
            atomicExch(&d_fin, 0u);
        }
    }
}

// ---------------------------------------------------------------------------
// K2: out[i,j] = h[i] + g[i]*w1bar[j] — the proven 37.4 us configuration:
// 16 rows/block, 4000 blocks, 26 regs, no smem, streaming float4 stores.
// ---------------------------------------------------------------------------
__global__ void k_outer(float* __restrict__ out)
{
    int j4 = blockIdx.x * OUT_TPB + threadIdx.x;
    if (j4 >= N4) return;

    float4 w4 = reinterpret_cast<const float4*>(d_w1bar)[j4];
    int i0 = blockIdx.y * ROWS_PER_BLK;
    float4* o4 = reinterpret_cast<float4*>(out);

#pragma unroll
    for (int k = 0; k < ROWS_PER_BLK; k++) {
        int i = i0 + k;
        float gv = d_g[i];
        float hv = d_h[i];
        float4 o;
        o.x = fmaf(gv, w4.x, hv);
        o.y = fmaf(gv, w4.y, hv);
        o.z = fmaf(gv, w4.z, hv);
        o.w = fmaf(gv, w4.w, hv);
        __stcs(&o4[(size_t)i * N4 + j4], o);
    }
}

// ---------------------------------------------------------------------------
extern "C" void kernel_launch(void* const* d_in, const int* in_sizes, int n_in,
                              void* d_out, int out_size)
{
    const float* x   = (const float*)d_in[0];
    const float* a1  = (const float*)d_in[1];
    const float* c1  = (const float*)d_in[2];
    const float* a2  = (const float*)d_in[3];
    const float* c2  = (const float*)d_in[4];
    const float* wf1 = (const float*)d_in[5];
    const float* bf1 = (const float*)d_in[6];
    const float* wf2 = (const float*)d_in[7];
    const float* bf2 = (const float*)d_in[8];
    float* out = (float*)d_out;

    k_pro<<<NB1, K1_TPB>>>(x, a1, c1, a2, c2, wf1, bf1, wf2, bf2);

    dim3 grid((N4 + OUT_TPB - 1) / OUT_TPB, N_ROWS / ROWS_PER_BLK);  // (8, 500)
    k_outer<<<grid, OUT_TPB>>>(out);
}

// round 11
// speedup vs baseline: 1.0028x; 1.0028x over previous
#include <cuda_runtime.h>

#define N_ROWS 8000
#define D 9
#define N4 2000            // N_ROWS / 4 (float4 columns)
#define OUT_TPB 256
#define ROWS_PER_BLK 16
#define CHUNK 64           // rows per prologue block
#define NB1 125            // 125 * 64 = 8000
#define K1_TPB 64

// Scratch (device globals — no allocation allowed)
__device__ float d_csum[NB1];       // per-chunk totals
__device__ float d_delta[N_ROWS];   // within-chunk inclusive cumsum
__device__ float d_w1bar[N_ROWS];
__device__ float d_g[N_ROWS];
__device__ float d_h[N_ROWS];

// ---------------------------------------------------------------------------
// K1: rowstats + within-chunk scan. Pure dataflow — no atomics, no fences.
//   delta[r] = sum_d [ ((x-c1)/a1)^2 - ((x-c2)/a2)^2 ]   (log-domain)
//   d_delta[r] = inclusive cumsum of delta within the 64-row chunk
//   d_csum[b]  = chunk total
//   g[r] = f1[r]-f2[r],  h[r] = f2[r]
// ---------------------------------------------------------------------------
__global__ void __launch_bounds__(K1_TPB)
k_pro(const float* __restrict__ x,
      const float* __restrict__ a1, const float* __restrict__ c1,
      const float* __restrict__ a2, const float* __restrict__ c2,
      const float* __restrict__ wf1, const float* __restrict__ bf1,
      const float* __restrict__ wf2, const float* __restrict__ bf2)
{
    __shared__ float s_w0tot;

    const int t = threadIdx.x;
    const int b = blockIdx.x;
    const unsigned lane = t & 31;
    const int w = t >> 5;

    const int r = b * CHUNK + t;
    const float inv1 = 1.0f / __ldg(a1);
    const float inv2 = 1.0f / __ldg(a2);
    const float k1 = -__ldg(c1) * inv1;
    const float k2 = -__ldg(c2) * inv2;
    float s1 = 0.f, s2 = 0.f;
    float f1 = __ldg(bf1), f2 = __ldg(bf2);
#pragma unroll
    for (int d = 0; d < D; d++) {
        float xv = __ldg(&x[r * D + d]);
        float u1 = fmaf(xv, inv1, k1);
        float u2 = fmaf(xv, inv2, k2);
        s1 = fmaf(u1, u1, s1);
        s2 = fmaf(u2, u2, s2);
        f1 = fmaf(xv, __ldg(&wf1[d]), f1);
        f2 = fmaf(xv, __ldg(&wf2[d]), f2);
    }
    d_g[r] = f1 - f2;
    d_h[r] = f2;

    // within-chunk inclusive cumsum (2 warps)
    float v = s1 - s2;
#pragma unroll
    for (int o = 1; o < 32; o <<= 1) {
        float n = __shfl_up_sync(0xffffffff, v, o);
        if (lane >= o) v += n;
    }
    if (t == 31) s_w0tot = v;
    __syncthreads();
    if (w == 1) v += s_w0tot;
    d_delta[r] = v;
    if (t == CHUNK - 1) d_csum[b] = v;
}

// ---------------------------------------------------------------------------
// K2: each block computes ITS OWN chunk prefix by reduction over csum[0..b-1]
// (<=124 L2-hot floats) — no cross-block sync of any kind — then applies:
//   w1bar[r] = 1/(1+exp(pref + d_delta[r]))
// ---------------------------------------------------------------------------
__global__ void __launch_bounds__(K1_TPB)
k_apply()
{
    __shared__ float swt[2];

    const int t = threadIdx.x;
    const int b = blockIdx.x;
    const unsigned lane = t & 31;
    const int w = t >> 5;

    // reduce csum[0..b-1]
    float s = 0.0f;
    if (t < b)      s += d_csum[t];
    if (t + 64 < b) s += d_csum[t + 64];
#pragma unroll
    for (int o = 16; o > 0; o >>= 1)
        s += __shfl_down_sync(0xffffffff, s, o);
    if (lane == 0) swt[w] = s;
    __syncthreads();
    const float pref = swt[0] + swt[1];

    const int r = b * CHUNK + t;
    const float run = pref + d_delta[r];        // S1[r] - S2[r]
    d_w1bar[r] = 1.0f / (1.0f + __expf(run));   // stable 2-rule softmax
}

// ---------------------------------------------------------------------------
// K3: out[i,j] = h[i] + g[i]*w1bar[j] — proven roofline shape
// (16 rows/block, 4000 blocks, no smem). Experiment: plain writeback stores
// (drop __stcs) to let L2 absorb the dirty tail.
// ---------------------------------------------------------------------------
__global__ void k_outer(float* __restrict__ out)
{
    int j4 = blockIdx.x * OUT_TPB + threadIdx.x;
    if (j4 >= N4) return;

    float4 w4 = reinterpret_cast<const float4*>(d_w1bar)[j4];
    int i0 = blockIdx.y * ROWS_PER_BLK;
    float4* o4 = reinterpret_cast<float4*>(out);

#pragma unroll
    for (int k = 0; k < ROWS_PER_BLK; k++) {
        int i = i0 + k;
        float gv = d_g[i];
        float hv = d_h[i];
        float4 o;
        o.x = fmaf(gv, w4.x, hv);
        o.y = fmaf(gv, w4.y, hv);
        o.z = fmaf(gv, w4.z, hv);
        o.w = fmaf(gv, w4.w, hv);
        o4[(size_t)i * N4 + j4] = o;            // writeback (no evict hint)
    }
}

// ---------------------------------------------------------------------------
extern "C" void kernel_launch(void* const* d_in, const int* in_sizes, int n_in,
                              void* d_out, int out_size)
{
    const float* x   = (const float*)d_in[0];
    const float* a1  = (const float*)d_in[1];
    const float* c1  = (const float*)d_in[2];
    const float* a2  = (const float*)d_in[3];
    const float* c2  = (const float*)d_in[4];
    const float* wf1 = (const float*)d_in[5];
    const float* bf1 = (const float*)d_in[6];
    const float* wf2 = (const float*)d_in[7];
    const float* bf2 = (const float*)d_in[8];
    float* out = (float*)d_out;

    k_pro<<<NB1, K1_TPB>>>(x, a1, c1, a2, c2, wf1, bf1, wf2, bf2);
    k_apply<<<NB1, K1_TPB>>>();

    dim3 grid((N4 + OUT_TPB - 1) / OUT_TPB, N_ROWS / ROWS_PER_BLK);  // (8, 500)
    k_outer<<<grid, OUT_TPB>>>(out);
}